// round 8
// baseline (speedup 1.0000x reference)
#include <cuda_runtime.h>
#include <math.h>

#define PI_F 3.14159265358979323846f

// ---------- helpers ----------
__device__ __forceinline__ float2 cmul(float2 a, float2 b){
    return make_float2(a.x*b.x - a.y*b.y, a.x*b.y + a.y*b.x);
}
__device__ __forceinline__ float2 cadd(float2 a, float2 b){ return make_float2(a.x+b.x, a.y+b.y); }
__device__ __forceinline__ float2 expi(float a){ float s,c; __sincosf(a,&s,&c); return make_float2(c,s); }
__device__ __forceinline__ float2 cscale(float2 a, float s){ return make_float2(a.x*s, a.y*s); }
__device__ __forceinline__ float2 shflx(float2 v, int m){
    return make_float2(__shfl_xor_sync(0xffffffffu, v.x, m),
                       __shfl_xor_sync(0xffffffffu, v.y, m));
}
__device__ __forceinline__ float fast_tanh(float x){
    float e = __expf(2.f * x);
    return 1.f - 2.f / (e + 1.f);
}
// packed f32x2
__device__ __forceinline__ unsigned long long pk2(float x, float y){
    unsigned long long r; asm("mov.b64 %0, {%1,%2};" : "=l"(r) : "f"(x), "f"(y)); return r;
}
__device__ __forceinline__ float2 upk2(unsigned long long a){
    float2 r; asm("mov.b64 {%0,%1}, %2;" : "=f"(r.x), "=f"(r.y) : "l"(a)); return r;
}
__device__ __forceinline__ unsigned long long fma2(unsigned long long a, unsigned long long b,
                                                   unsigned long long c){
    unsigned long long d;
    asm("fma.rn.f32x2 %0, %1, %2, %3;" : "=l"(d) : "l"(a), "l"(b), "l"(c));
    return d;
}

// fully-unrolled 8-gate initQKV circuit on 16 amplitudes across a 16-lane group
__device__ __forceinline__ float2 sim16(const float* __restrict__ rot,
                                        const float* __restrict__ crx,
                                        int col, int lane)
{
    float2 s = (lane == col) ? make_float2(1.f, 0.f) : make_float2(0.f, 0.f);
    #pragma unroll
    for (int g = 0; g < 8; g++){
        const int pa_[8] = {0,1,2,3,0,1,2,3};
        const int pb_[8] = {1,2,3,0,3,0,1,2};
        const int ma = 8 >> pa_[g], mb = 8 >> pb_[g];

        float phi = rot[3*g], th = rot[3*g+1], om = rot[3*g+2];
        float c, sn; __sincosf(0.5f*th, &sn, &c);
        float2 u00 = cscale(expi(-0.5f*(phi+om)),  c);
        float2 u01 = cscale(expi( 0.5f*(phi-om)), -sn);
        float2 u10 = cscale(expi(-0.5f*(phi-om)),  sn);
        float2 u11 = cscale(expi( 0.5f*(phi+om)),  c);
        float2 o = shflx(s, ma);
        s = (lane & ma) ? cadd(cmul(u10, o), cmul(u11, s))
                        : cadd(cmul(u00, s), cmul(u01, o));

        float cc, ss; __sincosf(0.5f*crx[g], &ss, &cc);
        o = shflx(s, mb);
        if (lane & ma) s = make_float2(cc*s.x + ss*o.y, cc*s.y - ss*o.x);

        o = shflx(s, mb);
        if (lane & ma) s = o;
    }
    return s;
}

// One fused kernel. 544 threads:
//  preamble: 34 groups of 16 lanes run sim16 in parallel (U_q cols 0-15, U_v cols 16-31, k 32/33)
//  main: 68 samples x 8 lanes. Lane o (t&7) holds amplitude rows 2o, 2o+1.
//  wires: wire0 <-> lane^4, wire1 <-> lane^2, wire2 <-> lane^1, wire3 <-> register pair.
__global__ void __launch_bounds__(544, 2)
qc_kernel(const float* __restrict__ x1, const float* __restrict__ pre_w,
          const float* __restrict__ pre_b,
          const float* __restrict__ q_rot, const float* __restrict__ k_rot,
          const float* __restrict__ v_rot,
          const float* __restrict__ q_crx, const float* __restrict__ k_crx,
          const float* __restrict__ v_crx,
          const float* __restrict__ ln_w, const float* __restrict__ ln_b,
          const float* __restrict__ head_w, const float* __restrict__ head_b,
          float* __restrict__ out, int B)
{
    __shared__ float4 sUq[128];   // 16x16 complex, odd-parity columns pre-rotated by (-i)
    __shared__ float4 sUv[128];
    __shared__ float  sW[384];    // pre_w [4][96]
    __shared__ float  sKx[4];
    __shared__ float  sPB[4];
    __shared__ float  sLnW[8], sLnB[8], sHW[16], sHB[2];

    int t = threadIdx.x;

    for (int i = t; i < 384; i += 544) sW[i] = pre_w[i];
    if (t < 4)              sPB[t]     = pre_b[t];
    if (t >= 4 && t < 12)   sLnW[t-4]  = ln_w[t-4];
    if (t >= 12 && t < 20)  sLnB[t-12] = ln_b[t-12];
    if (t >= 20 && t < 36)  sHW[t-20]  = head_w[t-20];
    if (t >= 36 && t < 38)  sHB[t-36]  = head_b[t-36];

    // ---- parallel setup ----
    {
        int grp  = t >> 4;      // 0..33
        int lane = t & 15;
        const float* rot; const float* crx; int col;
        if (grp < 16)      { rot = q_rot; crx = q_crx; col = grp;      }
        else if (grp < 32) { rot = v_rot; crx = v_crx; col = grp - 16; }
        else               { rot = k_rot; crx = k_crx; col = 0;        }

        float2 s = sim16(rot, crx, col, lane);

        if (grp < 32){
            float2 sp = (__popc(col) & 1) ? make_float2(s.y, -s.x) : s;  // pre-rotate by (-i)
            float2* dst = (grp < 16) ? (float2*)sUq : (float2*)sUv;
            dst[col*16 + lane] = sp;
        } else {
            #pragma unroll
            for (int w = 0; w < 4; w++){
                int m = 8 >> w;
                float2 o = shflx(s, m);
                float v = s.x*o.x + s.y*o.y;
                v += __shfl_xor_sync(0xffffffffu, v, 1);
                v += __shfl_xor_sync(0xffffffffu, v, 2);
                v += __shfl_xor_sync(0xffffffffu, v, 4);
                v += __shfl_xor_sync(0xffffffffu, v, 8);
                if (grp == 32 && lane == 0) sKx[w] = v;
            }
        }
    }
    __syncthreads();

    // ---- main phase: 8 lanes per sample ----
    int s_idx = blockIdx.x * 68 + (t >> 3);
    int o     = t & 7;                       // octet lane: rows 2o, 2o+1
    if (s_idx >= B) return;

    const float4* sW4 = (const float4*)sW;

    // x = x1[s] @ pre_w.T + pre_b : each lane 12 of 96 elements, 3-step butterfly
    float a0 = 0.f, a1 = 0.f, a2 = 0.f, a3 = 0.f;
    {
        const float4* row = (const float4*)(x1 + (size_t)s_idx * 96) + o * 3;
        #pragma unroll
        for (int k = 0; k < 3; k++){
            float4 v = row[k];
            float4 w0 = sW4[      o*3 + k];
            float4 w1 = sW4[ 24 + o*3 + k];
            float4 w2 = sW4[ 48 + o*3 + k];
            float4 w3 = sW4[ 72 + o*3 + k];
            a0 += v.x*w0.x + v.y*w0.y + v.z*w0.z + v.w*w0.w;
            a1 += v.x*w1.x + v.y*w1.y + v.z*w1.z + v.w*w1.w;
            a2 += v.x*w2.x + v.y*w2.y + v.z*w2.z + v.w*w2.w;
            a3 += v.x*w3.x + v.y*w3.y + v.z*w3.z + v.w*w3.w;
        }
        #pragma unroll
        for (int d = 1; d <= 4; d <<= 1){
            a0 += __shfl_xor_sync(0xffffffffu, a0, d);
            a1 += __shfl_xor_sync(0xffffffffu, a1, d);
            a2 += __shfl_xor_sync(0xffffffffu, a2, d);
            a3 += __shfl_xor_sync(0xffffffffu, a3, d);
        }
    }
    float xw[4] = { a0 + sPB[0], a1 + sPB[1], a2 + sPB[2], a3 + sPB[3] };

    float hc[4], hs[4];
    #pragma unroll
    for (int w = 0; w < 4; w++) __sincosf(0.5f * xw[w], &hs[w], &hc[w]);

    // product state magnitudes, (-1) part of (-i)^popc folded in ((-i) is in U)
    float m[16];
    #pragma unroll
    for (int i = 0; i < 16; i++){
        float v = ((i&8)?hs[0]:hc[0]) * ((i&4)?hs[1]:hc[1]) * ((i&2)?hs[2]:hc[2]) * ((i&1)?hs[3]:hc[3]);
        m[i] = (__popc(i) & 2) ? -v : v;
    }

    // ---- both matvecs (rows 2o, 2o+1), packed f32x2 FMA ----
    unsigned long long pq0 = 0ull, pq1 = 0ull, pv0 = 0ull, pv1 = 0ull;
    #pragma unroll
    for (int j = 0; j < 16; j++){
        unsigned long long mj2 = pk2(m[j], m[j]);
        float4 q = sUq[j*8 + o];
        float4 v = sUv[j*8 + o];
        pq0 = fma2(pk2(q.x,q.y), mj2, pq0);
        pq1 = fma2(pk2(q.z,q.w), mj2, pq1);
        pv0 = fma2(pk2(v.x,v.y), mj2, pv0);
        pv1 = fma2(pk2(v.z,v.w), mj2, pv1);
    }
    float2 stq[2] = { upk2(pq0), upk2(pq1) };
    float2 stv[2] = { upk2(pv0), upk2(pv1) };

    // ---- q path: RX(x) layer (symmetric pair update) ----
    #pragma unroll
    for (int w = 0; w < 3; w++){
        int d = 4 >> w;   // wire0: lane^4, wire1: lane^2, wire2: lane^1
        float c = hc[w], s = hs[w];
        #pragma unroll
        for (int r = 0; r < 2; r++){
            float2 p = shflx(stq[r], d);
            stq[r] = make_float2(c*stq[r].x + s*p.y, c*stq[r].y - s*p.x);
        }
    }
    {   // wire3: register pair
        float c = hc[3], s = hs[3];
        float2 n0 = make_float2(c*stq[0].x + s*stq[1].y, c*stq[0].y - s*stq[1].x);
        float2 n1 = make_float2(c*stq[1].x + s*stq[0].y, c*stq[1].y - s*stq[0].x);
        stq[0] = n0; stq[1] = n1;
    }

    // ---- scores: z_w = <Z_w>, x_w = <X_w> * kx_w ----
    {
        float n0 = stq[0].x*stq[0].x + stq[0].y*stq[0].y;
        float n1 = stq[1].x*stq[1].x + stq[1].y*stq[1].y;
        float tt = n0 + n1;
        float z0 = (o & 4) ? -tt : tt;
        float z1 = (o & 2) ? -tt : tt;
        float z2 = (o & 1) ? -tt : tt;
        float z3 = n0 - n1;

        float2 p00 = shflx(stq[0], 4), p01 = shflx(stq[1], 4);
        float x0 = stq[0].x*p00.x + stq[0].y*p00.y + stq[1].x*p01.x + stq[1].y*p01.y;
        float2 p10 = shflx(stq[0], 2), p11 = shflx(stq[1], 2);
        float x1m = stq[0].x*p10.x + stq[0].y*p10.y + stq[1].x*p11.x + stq[1].y*p11.y;
        float2 p20 = shflx(stq[0], 1), p21 = shflx(stq[1], 1);
        float x2 = stq[0].x*p20.x + stq[0].y*p20.y + stq[1].x*p21.x + stq[1].y*p21.y;
        float x3 = 2.f*(stq[0].x*stq[1].x + stq[0].y*stq[1].y);

        #pragma unroll
        for (int d = 1; d <= 4; d <<= 1){
            z0 += __shfl_xor_sync(0xffffffffu, z0, d);
            z1 += __shfl_xor_sync(0xffffffffu, z1, d);
            z2 += __shfl_xor_sync(0xffffffffu, z2, d);
            z3 += __shfl_xor_sync(0xffffffffu, z3, d);
            x0 += __shfl_xor_sync(0xffffffffu, x0, d);
            x1m+= __shfl_xor_sync(0xffffffffu, x1m, d);
            x2 += __shfl_xor_sync(0xffffffffu, x2, d);
            x3 += __shfl_xor_sync(0xffffffffu, x3, d);
        }
        x0 *= sKx[0]; x1m *= sKx[1]; x2 *= sKx[2]; x3 *= sKx[3];

        float rz0 = fast_tanh(sqrtf(z0*z0 + x0*x0))   * (0.5f * PI_F);
        float rz1 = fast_tanh(sqrtf(z1*z1 + x1m*x1m)) * (0.5f * PI_F);
        float rz2 = fast_tanh(sqrtf(z2*z2 + x2*x2))   * (0.5f * PI_F);
        float rz3 = fast_tanh(sqrtf(z3*z3 + x3*x3))   * (0.5f * PI_F);

        // ---- v path: RZ phases (bit set -> +rz, clear -> -rz) ----
        float phl = ((o & 4) ? rz0 : -rz0) + ((o & 2) ? rz1 : -rz1) + ((o & 1) ? rz2 : -rz2);
        {
            float ph0 = phl - rz3, ph1 = phl + rz3;
            float sp, cp;
            __sincosf(ph0, &sp, &cp);
            stv[0] = make_float2(stv[0].x*cp - stv[0].y*sp, stv[0].x*sp + stv[0].y*cp);
            __sincosf(ph1, &sp, &cp);
            stv[1] = make_float2(stv[1].x*cp - stv[1].y*sp, stv[1].x*sp + stv[1].y*cp);
        }
    }

    // CNOT(0,1): if wire0 set (o&4), take value from lane with wire1 flipped (o^2)
    {
        float2 p0 = shflx(stv[0], 2), p1 = shflx(stv[1], 2);
        if (o & 4){ stv[0] = p0; stv[1] = p1; }
    }
    // CNOT(1,2): if wire1 set (o&2), take from lane o^1
    {
        float2 p0 = shflx(stv[0], 1), p1 = shflx(stv[1], 1);
        if (o & 2){ stv[0] = p0; stv[1] = p1; }
    }
    // CNOT(2,3): if wire2 set (o&1), swap registers
    if (o & 1){ float2 tq = stv[0]; stv[0] = stv[1]; stv[1] = tq; }

    // ---- final expectations ----
    float n0 = stv[0].x*stv[0].x + stv[0].y*stv[0].y;
    float n1 = stv[1].x*stv[1].x + stv[1].y*stv[1].y;
    float tt = n0 + n1;
    float o0 = (o & 4) ? -tt : tt;
    float o1 = (o & 2) ? -tt : tt;
    float o2 = (o & 1) ? -tt : tt;
    float o3 = n0 - n1;

    float2 p00 = shflx(stv[0], 4), p01 = shflx(stv[1], 4);
    float o4 = stv[0].x*p00.x + stv[0].y*p00.y + stv[1].x*p01.x + stv[1].y*p01.y;
    float2 p10 = shflx(stv[0], 2), p11 = shflx(stv[1], 2);
    float o5 = stv[0].x*p10.x + stv[0].y*p10.y + stv[1].x*p11.x + stv[1].y*p11.y;
    float2 p20 = shflx(stv[0], 1), p21 = shflx(stv[1], 1);
    float o6 = stv[0].x*p20.x + stv[0].y*p20.y + stv[1].x*p21.x + stv[1].y*p21.y;
    float o7 = 2.f*(stv[0].x*stv[1].x + stv[0].y*stv[1].y);

    #pragma unroll
    for (int d = 1; d <= 4; d <<= 1){
        o0 += __shfl_xor_sync(0xffffffffu, o0, d);
        o1 += __shfl_xor_sync(0xffffffffu, o1, d);
        o2 += __shfl_xor_sync(0xffffffffu, o2, d);
        o3 += __shfl_xor_sync(0xffffffffu, o3, d);
        o4 += __shfl_xor_sync(0xffffffffu, o4, d);
        o5 += __shfl_xor_sync(0xffffffffu, o5, d);
        o6 += __shfl_xor_sync(0xffffffffu, o6, d);
        o7 += __shfl_xor_sync(0xffffffffu, o7, d);
    }

    if (o == 0){
        float ov[8] = { o0, o1, o2, o3, o4, o5, o6, o7 };
        float mu = 0.f;
        #pragma unroll
        for (int k = 0; k < 8; k++) mu += ov[k];
        mu *= 0.125f;
        float var = 0.f;
        #pragma unroll
        for (int k = 0; k < 8; k++){ float dd = ov[k] - mu; var += dd * dd; }
        var *= 0.125f;
        float inv = rsqrtf(var + 1e-5f);

        float r0 = sHB[0], r1 = sHB[1];
        #pragma unroll
        for (int k = 0; k < 8; k++){
            float y = (ov[k] - mu) * inv * sLnW[k] + sLnB[k];
            float g = 0.5f * y * (1.f + erff(y * 0.70710678118654752f));
            r0 += g * sHW[k];
            r1 += g * sHW[8 + k];
        }
        ((float2*)out)[s_idx] = make_float2(r0, r1);
    }
}

extern "C" void kernel_launch(void* const* d_in, const int* in_sizes, int n_in,
                              void* d_out, int out_size)
{
    const float* x1     = (const float*)d_in[0];
    const float* pre_w  = (const float*)d_in[1];
    const float* pre_b  = (const float*)d_in[2];
    const float* q_rot  = (const float*)d_in[3];
    const float* k_rot  = (const float*)d_in[4];
    const float* v_rot  = (const float*)d_in[5];
    const float* q_crx  = (const float*)d_in[6];
    const float* k_crx  = (const float*)d_in[7];
    const float* v_crx  = (const float*)d_in[8];
    const float* ln_w   = (const float*)d_in[9];
    const float* ln_b   = (const float*)d_in[10];
    const float* head_w = (const float*)d_in[11];
    const float* head_b = (const float*)d_in[12];

    int B = in_sizes[0] / 96;
    int blocks = (B + 67) / 68;

    qc_kernel<<<blocks, 544>>>(x1, pre_w, pre_b, q_rot, k_rot, v_rot,
                               q_crx, k_crx, v_crx, ln_w, ln_b, head_w, head_b,
                               (float*)d_out, B);
}

// round 9
// speedup vs baseline: 1.2735x; 1.2735x over previous
#include <cuda_runtime.h>
#include <math.h>

#define PI_F 3.14159265358979323846f

// Precomputed circuit data (setup_kernel -> qc_kernel)
// Odd-parity columns pre-rotated by (-i) so the matvec is a uniform f32x2 FMA.
__device__ float2 g_Uq[16][16];   // [col j][row i]
__device__ float2 g_Uv[16][16];
__device__ float  g_kx[4];        // <X_w> of the fixed k-register state

// ---------- helpers ----------
__device__ __forceinline__ float2 cmul(float2 a, float2 b){
    return make_float2(a.x*b.x - a.y*b.y, a.x*b.y + a.y*b.x);
}
__device__ __forceinline__ float2 cadd(float2 a, float2 b){ return make_float2(a.x+b.x, a.y+b.y); }
__device__ __forceinline__ float2 expi(float a){ float s,c; __sincosf(a,&s,&c); return make_float2(c,s); }
__device__ __forceinline__ float2 cscale(float2 a, float s){ return make_float2(a.x*s, a.y*s); }
__device__ __forceinline__ float2 shflx(float2 v, int m){
    return make_float2(__shfl_xor_sync(0xffffffffu, v.x, m),
                       __shfl_xor_sync(0xffffffffu, v.y, m));
}
__device__ __forceinline__ float fast_tanh(float x){
    float e = __expf(2.f * x);
    return 1.f - 2.f / (e + 1.f);
}
__device__ __forceinline__ unsigned long long pk2(float x, float y){
    unsigned long long r; asm("mov.b64 %0, {%1,%2};" : "=l"(r) : "f"(x), "f"(y)); return r;
}
__device__ __forceinline__ float2 upk2(unsigned long long a){
    float2 r; asm("mov.b64 {%0,%1}, %2;" : "=f"(r.x), "=f"(r.y) : "l"(a)); return r;
}
__device__ __forceinline__ unsigned long long fma2(unsigned long long a, unsigned long long b,
                                                   unsigned long long c){
    unsigned long long d;
    asm("fma.rn.f32x2 %0, %1, %2, %3;" : "=l"(d) : "l"(a), "l"(b), "l"(c));
    return d;
}

// fully-unrolled 8-gate initQKV circuit on 16 amplitudes across a 16-lane group
__device__ __forceinline__ float2 sim16(const float* __restrict__ rot,
                                        const float* __restrict__ crx,
                                        int col, int lane)
{
    float2 s = (lane == col) ? make_float2(1.f, 0.f) : make_float2(0.f, 0.f);
    #pragma unroll
    for (int g = 0; g < 8; g++){
        const int pa_[8] = {0,1,2,3,0,1,2,3};
        const int pb_[8] = {1,2,3,0,3,0,1,2};
        const int ma = 8 >> pa_[g], mb = 8 >> pb_[g];

        float phi = rot[3*g], th = rot[3*g+1], om = rot[3*g+2];
        float c, sn; __sincosf(0.5f*th, &sn, &c);
        float2 u00 = cscale(expi(-0.5f*(phi+om)),  c);
        float2 u01 = cscale(expi( 0.5f*(phi-om)), -sn);
        float2 u10 = cscale(expi(-0.5f*(phi-om)),  sn);
        float2 u11 = cscale(expi( 0.5f*(phi+om)),  c);
        float2 o = shflx(s, ma);
        s = (lane & ma) ? cadd(cmul(u10, o), cmul(u11, s))
                        : cadd(cmul(u00, s), cmul(u01, o));

        float cc, ss; __sincosf(0.5f*crx[g], &ss, &cc);
        o = shflx(s, mb);
        if (lane & ma) s = make_float2(cc*s.x + ss*o.y, cc*s.y - ss*o.x);

        o = shflx(s, mb);
        if (lane & ma) s = o;
    }
    return s;
}

// 17 blocks x 32 threads: block b handles chains 2b, 2b+1.
__global__ void __launch_bounds__(32)
setup_kernel(const float* __restrict__ qr, const float* __restrict__ kr,
             const float* __restrict__ vr, const float* __restrict__ qc,
             const float* __restrict__ kc, const float* __restrict__ vc)
{
    int grp  = blockIdx.x * 2 + (threadIdx.x >> 4);   // 0..33
    int lane = threadIdx.x & 15;

    const float* rot; const float* crx; int col;
    if (grp < 16)      { rot = qr; crx = qc; col = grp;      }
    else if (grp < 32) { rot = vr; crx = vc; col = grp - 16; }
    else               { rot = kr; crx = kc; col = 0;        }

    float2 s = sim16(rot, crx, col, lane);

    if (grp < 32){
        if (__popc(col) & 1) s = make_float2(s.y, -s.x);   // pre-rotate by (-i)
        if (grp < 16) g_Uq[col][lane] = s;
        else          g_Uv[col][lane] = s;
    } else {
        #pragma unroll
        for (int w = 0; w < 4; w++){
            int m = 8 >> w;
            float2 o = shflx(s, m);
            float v = s.x*o.x + s.y*o.y;
            v += __shfl_xor_sync(0xffffffffu, v, 1);
            v += __shfl_xor_sync(0xffffffffu, v, 2);
            v += __shfl_xor_sync(0xffffffffu, v, 4);
            v += __shfl_xor_sync(0xffffffffu, v, 8);
            if (grp == 32 && lane == 0) g_kx[w] = v;
        }
    }
}

// 128 threads = 32 quads; each quad serves TWO samples (ILP-2). 64 samples/block.
__global__ void __launch_bounds__(128, 3)
qc_kernel(const float* __restrict__ x1, const float* __restrict__ pre_w,
          const float* __restrict__ pre_b,
          const float* __restrict__ ln_w, const float* __restrict__ ln_b,
          const float* __restrict__ head_w, const float* __restrict__ head_b,
          float* __restrict__ out, int B)
{
    __shared__ float4 sUq[128];   // 16x16 complex
    __shared__ float4 sUv[128];
    __shared__ float  sW[384];    // pre_w [4][96]
    __shared__ float  sKx[4];
    __shared__ float  sPB[4];
    __shared__ float  sLnW[8], sLnB[8], sHW[16], sHB[2];

    int t = threadIdx.x;

    sUq[t] = ((const float4*)g_Uq)[t];
    sUv[t] = ((const float4*)g_Uv)[t];
    for (int i = t; i < 384; i += 128) sW[i] = pre_w[i];
    if (t < 4)              { sPB[t] = pre_b[t]; sKx[t] = g_kx[t]; }
    if (t >= 4 && t < 12)   sLnW[t-4]  = ln_w[t-4];
    if (t >= 12 && t < 20)  sLnB[t-12] = ln_b[t-12];
    if (t >= 20 && t < 36)  sHW[t-20]  = head_w[t-20];
    if (t >= 36 && t < 38)  sHB[t-36]  = head_b[t-36];
    __syncthreads();

    int q = t >> 2;                      // quad id 0..31
    int l = t & 3;                       // quad lane: rows 4l..4l+3
    int sA = blockIdx.x * 64 + q;
    int sB = sA + 32;
    bool okA = sA < B, okB = sB < B;
    int sAl = okA ? sA : 0;
    int sBl = okB ? sB : 0;

    const float4* sW4 = (const float4*)sW;
    const ulonglong2* Uq64 = (const ulonglong2*)sUq;
    const ulonglong2* Uv64 = (const ulonglong2*)sUv;

    // ---- x = x1[s] @ pre_w.T + pre_b, both samples, shared weights ----
    float a0A=0.f,a1A=0.f,a2A=0.f,a3A=0.f, a0B=0.f,a1B=0.f,a2B=0.f,a3B=0.f;
    {
        const float4* rowA = (const float4*)(x1 + (size_t)sAl * 96) + l * 6;
        const float4* rowB = (const float4*)(x1 + (size_t)sBl * 96) + l * 6;
        #pragma unroll
        for (int k = 0; k < 6; k++){
            float4 vA = rowA[k];
            float4 vB = rowB[k];
            float4 w0 = sW4[      l*6 + k];
            float4 w1 = sW4[ 24 + l*6 + k];
            float4 w2 = sW4[ 48 + l*6 + k];
            float4 w3 = sW4[ 72 + l*6 + k];
            a0A += vA.x*w0.x + vA.y*w0.y + vA.z*w0.z + vA.w*w0.w;
            a1A += vA.x*w1.x + vA.y*w1.y + vA.z*w1.z + vA.w*w1.w;
            a2A += vA.x*w2.x + vA.y*w2.y + vA.z*w2.z + vA.w*w2.w;
            a3A += vA.x*w3.x + vA.y*w3.y + vA.z*w3.z + vA.w*w3.w;
            a0B += vB.x*w0.x + vB.y*w0.y + vB.z*w0.z + vB.w*w0.w;
            a1B += vB.x*w1.x + vB.y*w1.y + vB.z*w1.z + vB.w*w1.w;
            a2B += vB.x*w2.x + vB.y*w2.y + vB.z*w2.z + vB.w*w2.w;
            a3B += vB.x*w3.x + vB.y*w3.y + vB.z*w3.z + vB.w*w3.w;
        }
        #pragma unroll
        for (int d = 1; d <= 2; d <<= 1){
            a0A += __shfl_xor_sync(0xffffffffu, a0A, d);
            a1A += __shfl_xor_sync(0xffffffffu, a1A, d);
            a2A += __shfl_xor_sync(0xffffffffu, a2A, d);
            a3A += __shfl_xor_sync(0xffffffffu, a3A, d);
            a0B += __shfl_xor_sync(0xffffffffu, a0B, d);
            a1B += __shfl_xor_sync(0xffffffffu, a1B, d);
            a2B += __shfl_xor_sync(0xffffffffu, a2B, d);
            a3B += __shfl_xor_sync(0xffffffffu, a3B, d);
        }
    }

    float hcA[4], hsA[4], hcB[4], hsB[4];
    {
        float xwA[4] = { a0A + sPB[0], a1A + sPB[1], a2A + sPB[2], a3A + sPB[3] };
        float xwB[4] = { a0B + sPB[0], a1B + sPB[1], a2B + sPB[2], a3B + sPB[3] };
        #pragma unroll
        for (int w = 0; w < 4; w++){
            __sincosf(0.5f * xwA[w], &hsA[w], &hcA[w]);
            __sincosf(0.5f * xwB[w], &hsB[w], &hcB[w]);
        }
    }

    // product-state magnitudes ((-1) of (-i)^popc folded in; (-i) itself is in U)
    float mA[16], mB[16];
    #pragma unroll
    for (int i = 0; i < 16; i++){
        float vA = ((i&8)?hsA[0]:hcA[0]) * ((i&4)?hsA[1]:hcA[1]) * ((i&2)?hsA[2]:hcA[2]) * ((i&1)?hsA[3]:hcA[3]);
        float vB = ((i&8)?hsB[0]:hcB[0]) * ((i&4)?hsB[1]:hcB[1]) * ((i&2)?hsB[2]:hcB[2]) * ((i&1)?hsB[3]:hcB[3]);
        if (__popc(i) & 2){ vA = -vA; vB = -vB; }
        mA[i] = vA; mB[i] = vB;
    }

    // ---- matvecs: shared U loads serve both samples ----
    unsigned long long pqA[4], pvA[4], pqB[4], pvB[4];
    #pragma unroll
    for (int r = 0; r < 4; r++){ pqA[r]=0ull; pvA[r]=0ull; pqB[r]=0ull; pvB[r]=0ull; }
    #pragma unroll
    for (int j = 0; j < 16; j++){
        unsigned long long mjA = pk2(mA[j], mA[j]);
        unsigned long long mjB = pk2(mB[j], mB[j]);
        ulonglong2 qa = Uq64[j*8 + 2*l];
        ulonglong2 qb = Uq64[j*8 + 2*l + 1];
        ulonglong2 va = Uv64[j*8 + 2*l];
        ulonglong2 vb = Uv64[j*8 + 2*l + 1];
        pqA[0] = fma2(qa.x, mjA, pqA[0]);  pqB[0] = fma2(qa.x, mjB, pqB[0]);
        pqA[1] = fma2(qa.y, mjA, pqA[1]);  pqB[1] = fma2(qa.y, mjB, pqB[1]);
        pqA[2] = fma2(qb.x, mjA, pqA[2]);  pqB[2] = fma2(qb.x, mjB, pqB[2]);
        pqA[3] = fma2(qb.y, mjA, pqA[3]);  pqB[3] = fma2(qb.y, mjB, pqB[3]);
        pvA[0] = fma2(va.x, mjA, pvA[0]);  pvB[0] = fma2(va.x, mjB, pvB[0]);
        pvA[1] = fma2(va.y, mjA, pvA[1]);  pvB[1] = fma2(va.y, mjB, pvB[1]);
        pvA[2] = fma2(vb.x, mjA, pvA[2]);  pvB[2] = fma2(vb.x, mjB, pvB[2]);
        pvA[3] = fma2(vb.y, mjA, pvA[3]);  pvB[3] = fma2(vb.y, mjB, pvB[3]);
    }
    float2 stqA[4], stvA[4], stqB[4], stvB[4];
    #pragma unroll
    for (int r = 0; r < 4; r++){
        stqA[r] = upk2(pqA[r]); stvA[r] = upk2(pvA[r]);
        stqB[r] = upk2(pqB[r]); stvB[r] = upk2(pvB[r]);
    }

    // ---- q path: RX(x) layer (symmetric pair update), both samples ----
    #pragma unroll
    for (int w = 0; w < 2; w++){
        int d = 2 >> w;   // wire0: lane^2, wire1: lane^1
        float cA = hcA[w], sA_ = hsA[w], cB = hcB[w], sB_ = hsB[w];
        #pragma unroll
        for (int r = 0; r < 4; r++){
            float2 oA = shflx(stqA[r], d);
            float2 oB = shflx(stqB[r], d);
            stqA[r] = make_float2(cA*stqA[r].x + sA_*oA.y, cA*stqA[r].y - sA_*oA.x);
            stqB[r] = make_float2(cB*stqB[r].x + sB_*oB.y, cB*stqB[r].y - sB_*oB.x);
        }
    }
    {   // wire2 (bit1): rows r <-> r^2
        float c = hcA[2], s = hsA[2];
        float2 n0 = make_float2(c*stqA[0].x + s*stqA[2].y, c*stqA[0].y - s*stqA[2].x);
        float2 n2 = make_float2(c*stqA[2].x + s*stqA[0].y, c*stqA[2].y - s*stqA[0].x);
        float2 n1 = make_float2(c*stqA[1].x + s*stqA[3].y, c*stqA[1].y - s*stqA[3].x);
        float2 n3 = make_float2(c*stqA[3].x + s*stqA[1].y, c*stqA[3].y - s*stqA[1].x);
        stqA[0]=n0; stqA[1]=n1; stqA[2]=n2; stqA[3]=n3;
        c = hcB[2]; s = hsB[2];
        n0 = make_float2(c*stqB[0].x + s*stqB[2].y, c*stqB[0].y - s*stqB[2].x);
        n2 = make_float2(c*stqB[2].x + s*stqB[0].y, c*stqB[2].y - s*stqB[0].x);
        n1 = make_float2(c*stqB[1].x + s*stqB[3].y, c*stqB[1].y - s*stqB[3].x);
        n3 = make_float2(c*stqB[3].x + s*stqB[1].y, c*stqB[3].y - s*stqB[1].x);
        stqB[0]=n0; stqB[1]=n1; stqB[2]=n2; stqB[3]=n3;
    }
    {   // wire3 (bit0): rows r <-> r^1
        float c = hcA[3], s = hsA[3];
        float2 n0 = make_float2(c*stqA[0].x + s*stqA[1].y, c*stqA[0].y - s*stqA[1].x);
        float2 n1 = make_float2(c*stqA[1].x + s*stqA[0].y, c*stqA[1].y - s*stqA[0].x);
        float2 n2 = make_float2(c*stqA[2].x + s*stqA[3].y, c*stqA[2].y - s*stqA[3].x);
        float2 n3 = make_float2(c*stqA[3].x + s*stqA[2].y, c*stqA[3].y - s*stqA[2].x);
        stqA[0]=n0; stqA[1]=n1; stqA[2]=n2; stqA[3]=n3;
        c = hcB[3]; s = hsB[3];
        n0 = make_float2(c*stqB[0].x + s*stqB[1].y, c*stqB[0].y - s*stqB[1].x);
        n1 = make_float2(c*stqB[1].x + s*stqB[0].y, c*stqB[1].y - s*stqB[0].x);
        n2 = make_float2(c*stqB[2].x + s*stqB[3].y, c*stqB[2].y - s*stqB[3].x);
        n3 = make_float2(c*stqB[3].x + s*stqB[2].y, c*stqB[3].y - s*stqB[2].x);
        stqB[0]=n0; stqB[1]=n1; stqB[2]=n2; stqB[3]=n3;
    }

    // ---- scores (both samples) ----
    float rzA[4], rzB[4];
    {
        float n0 = stqA[0].x*stqA[0].x + stqA[0].y*stqA[0].y;
        float n1 = stqA[1].x*stqA[1].x + stqA[1].y*stqA[1].y;
        float n2 = stqA[2].x*stqA[2].x + stqA[2].y*stqA[2].y;
        float n3 = stqA[3].x*stqA[3].x + stqA[3].y*stqA[3].y;
        float nsum = n0 + n1 + n2 + n3;
        float z0A = (l & 2) ? -nsum : nsum;
        float z1A = (l & 1) ? -nsum : nsum;
        float z2A = n0 + n1 - n2 - n3;
        float z3A = n0 - n1 + n2 - n3;

        n0 = stqB[0].x*stqB[0].x + stqB[0].y*stqB[0].y;
        n1 = stqB[1].x*stqB[1].x + stqB[1].y*stqB[1].y;
        n2 = stqB[2].x*stqB[2].x + stqB[2].y*stqB[2].y;
        n3 = stqB[3].x*stqB[3].x + stqB[3].y*stqB[3].y;
        nsum = n0 + n1 + n2 + n3;
        float z0B = (l & 2) ? -nsum : nsum;
        float z1B = (l & 1) ? -nsum : nsum;
        float z2B = n0 + n1 - n2 - n3;
        float z3B = n0 - n1 + n2 - n3;

        float x0A = 0.f, x1A = 0.f, x0B = 0.f, x1B = 0.f;
        #pragma unroll
        for (int r = 0; r < 4; r++){
            float2 oA = shflx(stqA[r], 2);
            float2 oB = shflx(stqB[r], 2);
            x0A += stqA[r].x*oA.x + stqA[r].y*oA.y;
            x0B += stqB[r].x*oB.x + stqB[r].y*oB.y;
        }
        #pragma unroll
        for (int r = 0; r < 4; r++){
            float2 oA = shflx(stqA[r], 1);
            float2 oB = shflx(stqB[r], 1);
            x1A += stqA[r].x*oA.x + stqA[r].y*oA.y;
            x1B += stqB[r].x*oB.x + stqB[r].y*oB.y;
        }
        float x2A = 2.f*(stqA[0].x*stqA[2].x + stqA[0].y*stqA[2].y + stqA[1].x*stqA[3].x + stqA[1].y*stqA[3].y);
        float x3A = 2.f*(stqA[0].x*stqA[1].x + stqA[0].y*stqA[1].y + stqA[2].x*stqA[3].x + stqA[2].y*stqA[3].y);
        float x2B = 2.f*(stqB[0].x*stqB[2].x + stqB[0].y*stqB[2].y + stqB[1].x*stqB[3].x + stqB[1].y*stqB[3].y);
        float x3B = 2.f*(stqB[0].x*stqB[1].x + stqB[0].y*stqB[1].y + stqB[2].x*stqB[3].x + stqB[2].y*stqB[3].y);

        #pragma unroll
        for (int d = 1; d <= 2; d <<= 1){
            z0A += __shfl_xor_sync(0xffffffffu, z0A, d);
            z1A += __shfl_xor_sync(0xffffffffu, z1A, d);
            z2A += __shfl_xor_sync(0xffffffffu, z2A, d);
            z3A += __shfl_xor_sync(0xffffffffu, z3A, d);
            x0A += __shfl_xor_sync(0xffffffffu, x0A, d);
            x1A += __shfl_xor_sync(0xffffffffu, x1A, d);
            x2A += __shfl_xor_sync(0xffffffffu, x2A, d);
            x3A += __shfl_xor_sync(0xffffffffu, x3A, d);
            z0B += __shfl_xor_sync(0xffffffffu, z0B, d);
            z1B += __shfl_xor_sync(0xffffffffu, z1B, d);
            z2B += __shfl_xor_sync(0xffffffffu, z2B, d);
            z3B += __shfl_xor_sync(0xffffffffu, z3B, d);
            x0B += __shfl_xor_sync(0xffffffffu, x0B, d);
            x1B += __shfl_xor_sync(0xffffffffu, x1B, d);
            x2B += __shfl_xor_sync(0xffffffffu, x2B, d);
            x3B += __shfl_xor_sync(0xffffffffu, x3B, d);
        }
        x0A *= sKx[0]; x1A *= sKx[1]; x2A *= sKx[2]; x3A *= sKx[3];
        x0B *= sKx[0]; x1B *= sKx[1]; x2B *= sKx[2]; x3B *= sKx[3];

        rzA[0] = fast_tanh(sqrtf(z0A*z0A + x0A*x0A)) * (0.5f * PI_F);
        rzA[1] = fast_tanh(sqrtf(z1A*z1A + x1A*x1A)) * (0.5f * PI_F);
        rzA[2] = fast_tanh(sqrtf(z2A*z2A + x2A*x2A)) * (0.5f * PI_F);
        rzA[3] = fast_tanh(sqrtf(z3A*z3A + x3A*x3A)) * (0.5f * PI_F);
        rzB[0] = fast_tanh(sqrtf(z0B*z0B + x0B*x0B)) * (0.5f * PI_F);
        rzB[1] = fast_tanh(sqrtf(z1B*z1B + x1B*x1B)) * (0.5f * PI_F);
        rzB[2] = fast_tanh(sqrtf(z2B*z2B + x2B*x2B)) * (0.5f * PI_F);
        rzB[3] = fast_tanh(sqrtf(z3B*z3B + x3B*x3B)) * (0.5f * PI_F);
    }

    // ---- v path: RZ phases ----
    {
        float phlA = ((l & 2) ? rzA[0] : -rzA[0]) + ((l & 1) ? rzA[1] : -rzA[1]);
        float phlB = ((l & 2) ? rzB[0] : -rzB[0]) + ((l & 1) ? rzB[1] : -rzB[1]);
        #pragma unroll
        for (int r = 0; r < 4; r++){
            float phA = phlA + ((r & 2) ? rzA[2] : -rzA[2]) + ((r & 1) ? rzA[3] : -rzA[3]);
            float phB = phlB + ((r & 2) ? rzB[2] : -rzB[2]) + ((r & 1) ? rzB[3] : -rzB[3]);
            float spA, cpA, spB, cpB;
            __sincosf(phA, &spA, &cpA);
            __sincosf(phB, &spB, &cpB);
            stvA[r] = make_float2(stvA[r].x*cpA - stvA[r].y*spA, stvA[r].x*spA + stvA[r].y*cpA);
            stvB[r] = make_float2(stvB[r].x*cpB - stvB[r].y*spB, stvB[r].x*spB + stvB[r].y*cpB);
        }
    }
    // CNOT(0,1): lanes with (l&2) take partner (l^1)'s value
    #pragma unroll
    for (int r = 0; r < 4; r++){
        float2 oA = shflx(stvA[r], 1);
        float2 oB = shflx(stvB[r], 1);
        if (l & 2){ stvA[r] = oA; stvB[r] = oB; }
    }
    // CNOT(1,2): if (l&1): swap rows r <-> r^2
    if (l & 1){
        float2 tq = stvA[0]; stvA[0] = stvA[2]; stvA[2] = tq;
        tq = stvA[1]; stvA[1] = stvA[3]; stvA[3] = tq;
        tq = stvB[0]; stvB[0] = stvB[2]; stvB[2] = tq;
        tq = stvB[1]; stvB[1] = stvB[3]; stvB[3] = tq;
    }
    // CNOT(2,3): swap rows 2,3
    { float2 tq = stvA[2]; stvA[2] = stvA[3]; stvA[3] = tq;
      tq = stvB[2]; stvB[2] = stvB[3]; stvB[3] = tq; }

    // ---- final expectations ----
    float o0A,o1A,o2A,o3A,o4A,o5A,o6A,o7A, o0B,o1B,o2B,o3B,o4B,o5B,o6B,o7B;
    {
        float n0 = stvA[0].x*stvA[0].x + stvA[0].y*stvA[0].y;
        float n1 = stvA[1].x*stvA[1].x + stvA[1].y*stvA[1].y;
        float n2 = stvA[2].x*stvA[2].x + stvA[2].y*stvA[2].y;
        float n3 = stvA[3].x*stvA[3].x + stvA[3].y*stvA[3].y;
        float qs = n0 + n1 + n2 + n3;
        o0A = (l & 2) ? -qs : qs;
        o1A = (l & 1) ? -qs : qs;
        o2A = n0 + n1 - n2 - n3;
        o3A = n0 - n1 + n2 - n3;

        n0 = stvB[0].x*stvB[0].x + stvB[0].y*stvB[0].y;
        n1 = stvB[1].x*stvB[1].x + stvB[1].y*stvB[1].y;
        n2 = stvB[2].x*stvB[2].x + stvB[2].y*stvB[2].y;
        n3 = stvB[3].x*stvB[3].x + stvB[3].y*stvB[3].y;
        qs = n0 + n1 + n2 + n3;
        o0B = (l & 2) ? -qs : qs;
        o1B = (l & 1) ? -qs : qs;
        o2B = n0 + n1 - n2 - n3;
        o3B = n0 - n1 + n2 - n3;

        o4A = 0.f; o5A = 0.f; o4B = 0.f; o5B = 0.f;
        #pragma unroll
        for (int r = 0; r < 4; r++){
            float2 oA = shflx(stvA[r], 2);
            float2 oB = shflx(stvB[r], 2);
            o4A += stvA[r].x*oA.x + stvA[r].y*oA.y;
            o4B += stvB[r].x*oB.x + stvB[r].y*oB.y;
        }
        #pragma unroll
        for (int r = 0; r < 4; r++){
            float2 oA = shflx(stvA[r], 1);
            float2 oB = shflx(stvB[r], 1);
            o5A += stvA[r].x*oA.x + stvA[r].y*oA.y;
            o5B += stvB[r].x*oB.x + stvB[r].y*oB.y;
        }
        o6A = 2.f*(stvA[0].x*stvA[2].x + stvA[0].y*stvA[2].y + stvA[1].x*stvA[3].x + stvA[1].y*stvA[3].y);
        o7A = 2.f*(stvA[0].x*stvA[1].x + stvA[0].y*stvA[1].y + stvA[2].x*stvA[3].x + stvA[2].y*stvA[3].y);
        o6B = 2.f*(stvB[0].x*stvB[2].x + stvB[0].y*stvB[2].y + stvB[1].x*stvB[3].x + stvB[1].y*stvB[3].y);
        o7B = 2.f*(stvB[0].x*stvB[1].x + stvB[0].y*stvB[1].y + stvB[2].x*stvB[3].x + stvB[2].y*stvB[3].y);

        #pragma unroll
        for (int d = 1; d <= 2; d <<= 1){
            o0A += __shfl_xor_sync(0xffffffffu, o0A, d);
            o1A += __shfl_xor_sync(0xffffffffu, o1A, d);
            o2A += __shfl_xor_sync(0xffffffffu, o2A, d);
            o3A += __shfl_xor_sync(0xffffffffu, o3A, d);
            o4A += __shfl_xor_sync(0xffffffffu, o4A, d);
            o5A += __shfl_xor_sync(0xffffffffu, o5A, d);
            o6A += __shfl_xor_sync(0xffffffffu, o6A, d);
            o7A += __shfl_xor_sync(0xffffffffu, o7A, d);
            o0B += __shfl_xor_sync(0xffffffffu, o0B, d);
            o1B += __shfl_xor_sync(0xffffffffu, o1B, d);
            o2B += __shfl_xor_sync(0xffffffffu, o2B, d);
            o3B += __shfl_xor_sync(0xffffffffu, o3B, d);
            o4B += __shfl_xor_sync(0xffffffffu, o4B, d);
            o5B += __shfl_xor_sync(0xffffffffu, o5B, d);
            o6B += __shfl_xor_sync(0xffffffffu, o6B, d);
            o7B += __shfl_xor_sync(0xffffffffu, o7B, d);
        }
    }

    if (l == 0){
        float oA[8] = { o0A,o1A,o2A,o3A,o4A,o5A,o6A,o7A };
        float oB[8] = { o0B,o1B,o2B,o3B,o4B,o5B,o6B,o7B };
        #pragma unroll
        for (int pass = 0; pass < 2; pass++){
            float* o = pass ? oB : oA;
            bool ok  = pass ? okB : okA;
            int  s   = pass ? sB  : sA;
            if (!ok) continue;
            float mu = 0.f;
            #pragma unroll
            for (int k = 0; k < 8; k++) mu += o[k];
            mu *= 0.125f;
            float var = 0.f;
            #pragma unroll
            for (int k = 0; k < 8; k++){ float dd = o[k] - mu; var += dd * dd; }
            var *= 0.125f;
            float inv = rsqrtf(var + 1e-5f);
            float r0 = sHB[0], r1 = sHB[1];
            #pragma unroll
            for (int k = 0; k < 8; k++){
                float y = (o[k] - mu) * inv * sLnW[k] + sLnB[k];
                float g = 0.5f * y * (1.f + erff(y * 0.70710678118654752f));
                r0 += g * sHW[k];
                r1 += g * sHW[8 + k];
            }
            ((float2*)out)[s] = make_float2(r0, r1);
        }
    }
}

extern "C" void kernel_launch(void* const* d_in, const int* in_sizes, int n_in,
                              void* d_out, int out_size)
{
    const float* x1     = (const float*)d_in[0];
    const float* pre_w  = (const float*)d_in[1];
    const float* pre_b  = (const float*)d_in[2];
    const float* q_rot  = (const float*)d_in[3];
    const float* k_rot  = (const float*)d_in[4];
    const float* v_rot  = (const float*)d_in[5];
    const float* q_crx  = (const float*)d_in[6];
    const float* k_crx  = (const float*)d_in[7];
    const float* v_crx  = (const float*)d_in[8];
    const float* ln_w   = (const float*)d_in[9];
    const float* ln_b   = (const float*)d_in[10];
    const float* head_w = (const float*)d_in[11];
    const float* head_b = (const float*)d_in[12];

    int B = in_sizes[0] / 96;

    setup_kernel<<<17, 32>>>(q_rot, k_rot, v_rot, q_crx, k_crx, v_crx);
    qc_kernel<<<(B + 63) / 64, 128>>>(x1, pre_w, pre_b, ln_w, ln_b, head_w, head_b,
                                      (float*)d_out, B);
}